// round 3
// baseline (speedup 1.0000x reference)
#include <cuda_runtime.h>
#include <math.h>

#define SEQ   2048
#define DM    1024
#define HEADS 16
#define KVH   4
#define HD    64
#define GROUP 4

// Scratch (static device globals: allowed; no dynamic allocation)
__device__ float g_Q[SEQ * DM];          // [S][HEADS][64] post-proj (+RoPE)
__device__ float g_K[SEQ * KVH * HD];    // [S][KVH][64]
__device__ float g_V[SEQ * KVH * HD];    // [S][KVH][64]
__device__ float g_O[SEQ * DM];          // attention output [S][HEADS][64]

// ---------------------------------------------------------------------------
// Tiled GEMM + bias: C[M,N] = A[M,K] @ B[K,N] + bias[N]
// 64x64 tile, BK=16, 256 threads, 4x4 per thread.
// ---------------------------------------------------------------------------
__global__ void gemm_bias(const float* __restrict__ A, const float* __restrict__ B,
                          const float* __restrict__ bias, float* __restrict__ C,
                          int M, int N, int K) {
    __shared__ float As[16][65];   // [kk][m], padded
    __shared__ float Bs[16][64];   // [kk][n]
    int tid = threadIdx.x;
    int tx = tid & 15, ty = tid >> 4;
    int row0 = blockIdx.y * 64, col0 = blockIdx.x * 64;
    float acc[4][4] = {};

    for (int k0 = 0; k0 < K; k0 += 16) {
        {   // load A tile (64 rows x 16 k), float4 along k
            int m   = tid >> 2;
            int kk4 = (tid & 3) * 4;
            float4 a = *(const float4*)(A + (size_t)(row0 + m) * K + k0 + kk4);
            As[kk4 + 0][m] = a.x; As[kk4 + 1][m] = a.y;
            As[kk4 + 2][m] = a.z; As[kk4 + 3][m] = a.w;
        }
        {   // load B tile (16 k x 64 n), float4 along n
            int kk = tid >> 4;
            int n4 = (tid & 15) * 4;
            *(float4*)&Bs[kk][n4] = *(const float4*)(B + (size_t)(k0 + kk) * N + col0 + n4);
        }
        __syncthreads();
        #pragma unroll
        for (int kk = 0; kk < 16; kk++) {
            float av[4], bv[4];
            #pragma unroll
            for (int i = 0; i < 4; i++) av[i] = As[kk][ty * 4 + i];
            #pragma unroll
            for (int j = 0; j < 4; j++) bv[j] = Bs[kk][tx * 4 + j];
            #pragma unroll
            for (int i = 0; i < 4; i++)
                #pragma unroll
                for (int j = 0; j < 4; j++) acc[i][j] += av[i] * bv[j];
        }
        __syncthreads();
    }
    #pragma unroll
    for (int i = 0; i < 4; i++) {
        int r = row0 + ty * 4 + i;
        #pragma unroll
        for (int j = 0; j < 4; j++) {
            int c = col0 + tx * 4 + j;
            C[(size_t)r * N + c] = acc[i][j] + bias[c];
        }
    }
}

// ---------------------------------------------------------------------------
// RoPE (interleaved-pair convention, matching the reference exactly)
// thetas_i = 10000^(-2*(2i)/64), pair (x[2i], x[2i+1])
// ---------------------------------------------------------------------------
__global__ void rope_kernel(float* __restrict__ X, int Hn) {
    int g = blockIdx.x * blockDim.x + threadIdx.x;
    int total = SEQ * Hn * (HD / 2);
    if (g >= total) return;
    int i = g % (HD / 2);
    int h = (g / (HD / 2)) % Hn;
    int s = g / ((HD / 2) * Hn);
    float inv = powf(10000.0f, -(float)(2 * (2 * i)) / (float)HD);
    float fr = (float)s * inv;
    float sv, cv;
    sincosf(fr, &sv, &cv);
    float* p = X + ((size_t)s * Hn + h) * HD + 2 * i;
    float x0 = p[0], x1 = p[1];
    p[0] = x0 * cv - x1 * sv;
    p[1] = x0 * sv + x1 * cv;
}

// ---------------------------------------------------------------------------
// Causal flash attention, fp32.
// grid (SEQ/64, HEADS), 256 threads. BQ=64, BK=32, hd=64.
// Thread t: qr = t/4, c4 = t%4.
//   scores: handles keys j = jj*4 + c4 (jj=0..7)   -> conflict-free K reads
//   PV/out: handles dims d = g*16 + c4*4 + e       -> conflict-free V reads
// Online softmax over 4-lane groups (shfl_xor 1,2).
// NOTE: reference uses jnp.tile for GQA -> query head h maps to KV head h % KVH.
// ---------------------------------------------------------------------------
__global__ void attn_kernel() {
    __shared__ float Qs[64][68];
    __shared__ float Ks[32][68];
    __shared__ float Vs[32][68];
    __shared__ float Ps[64][34];

    int tid = threadIdx.x;
    int qr = tid >> 2;
    int c4 = tid & 3;
    int q0 = blockIdx.x * 64;
    int h  = blockIdx.y;
    int kvh = h % KVH;   // jnp.tile semantics (NOT h / GROUP)

    // load Q tile (64 x 64)
    #pragma unroll
    for (int i = 0; i < 4; i++) {
        int f = tid + i * 256;
        int r = f >> 4, d4 = (f & 15) * 4;
        *(float4*)&Qs[r][d4] =
            *(const float4*)(g_Q + ((size_t)(q0 + r) * HEADS + h) * HD + d4);
    }

    float acc[4][4] = {};
    float mprev = -INFINITY, lrow = 0.0f;
    int ntiles = q0 / 32 + 2;   // keys 0 .. q0+63

    for (int kt = 0; kt < ntiles; kt++) {
        int k0 = kt * 32;
        __syncthreads();   // previous tile's Ks/Vs fully consumed
        #pragma unroll
        for (int i = 0; i < 2; i++) {
            int f = tid + i * 256;
            int r = f >> 4, d4 = (f & 15) * 4;
            size_t off = ((size_t)(k0 + r) * KVH + kvh) * HD + d4;
            *(float4*)&Ks[r][d4] = *(const float4*)(g_K + off);
            *(float4*)&Vs[r][d4] = *(const float4*)(g_V + off);
        }
        __syncthreads();

        // scores
        float s[8];
        #pragma unroll
        for (int jj = 0; jj < 8; jj++) {
            int j = jj * 4 + c4;
            float a = 0.0f;
            #pragma unroll
            for (int d = 0; d < 64; d++) a += Qs[qr][d] * Ks[j][d];
            s[jj] = a * 0.125f;
        }
        if (k0 + 31 > q0 + qr) {   // diagonal tiles: causal mask
            #pragma unroll
            for (int jj = 0; jj < 8; jj++)
                if (k0 + jj * 4 + c4 > q0 + qr) s[jj] = -INFINITY;
        }

        // online softmax (row spread over 4 lanes)
        float mloc = s[0];
        #pragma unroll
        for (int jj = 1; jj < 8; jj++) mloc = fmaxf(mloc, s[jj]);
        mloc = fmaxf(mloc, __shfl_xor_sync(0xffffffff, mloc, 1));
        mloc = fmaxf(mloc, __shfl_xor_sync(0xffffffff, mloc, 2));
        float mnew = fmaxf(mprev, mloc);
        float corr = __expf(mprev - mnew);
        float psum = 0.0f;
        #pragma unroll
        for (int jj = 0; jj < 8; jj++) {
            float p = __expf(s[jj] - mnew);
            Ps[qr][jj * 4 + c4] = p;
            psum += p;
        }
        psum += __shfl_xor_sync(0xffffffff, psum, 1);
        psum += __shfl_xor_sync(0xffffffff, psum, 2);
        lrow = lrow * corr + psum;
        mprev = mnew;
        #pragma unroll
        for (int g = 0; g < 4; g++)
            #pragma unroll
            for (int e = 0; e < 4; e++) acc[g][e] *= corr;

        __syncwarp();   // Ps written/read within the same 4-lane group's warp

        // PV
        #pragma unroll 4
        for (int k = 0; k < 32; k++) {
            float p = Ps[qr][k];
            #pragma unroll
            for (int g = 0; g < 4; g++) {
                float4 v = *(float4*)&Vs[k][g * 16 + c4 * 4];
                acc[g][0] += p * v.x; acc[g][1] += p * v.y;
                acc[g][2] += p * v.z; acc[g][3] += p * v.w;
            }
        }
    }

    float invl = 1.0f / lrow;
    float* outp = g_O + ((size_t)(q0 + qr) * HEADS + h) * HD;
    #pragma unroll
    for (int g = 0; g < 4; g++) {
        float4 v;
        v.x = acc[g][0] * invl; v.y = acc[g][1] * invl;
        v.z = acc[g][2] * invl; v.w = acc[g][3] * invl;
        *(float4*)(outp + g * 16 + c4 * 4) = v;
    }
}

// ---------------------------------------------------------------------------
// Launch
// Inputs (metadata order): q,k,v,mask,Wq,bq,Wk,bk,Wv,bv,Wo,bo
// ---------------------------------------------------------------------------
extern "C" void kernel_launch(void* const* d_in, const int* in_sizes, int n_in,
                              void* d_out, int out_size) {
    const float* q  = (const float*)d_in[0];
    const float* k  = (const float*)d_in[1];
    const float* v  = (const float*)d_in[2];
    const float* Wq = (const float*)d_in[4];
    const float* bq = (const float*)d_in[5];
    const float* Wk = (const float*)d_in[6];
    const float* bk = (const float*)d_in[7];
    const float* Wv = (const float*)d_in[8];
    const float* bv = (const float*)d_in[9];
    const float* Wo = (const float*)d_in[10];
    const float* bo = (const float*)d_in[11];
    float* out = (float*)d_out;

    float *gQ, *gK, *gV, *gO;
    cudaGetSymbolAddress((void**)&gQ, g_Q);
    cudaGetSymbolAddress((void**)&gK, g_K);
    cudaGetSymbolAddress((void**)&gV, g_V);
    cudaGetSymbolAddress((void**)&gO, g_O);

    // projections
    gemm_bias<<<dim3(DM / 64, SEQ / 64), 256>>>(q, Wq, bq, gQ, SEQ, DM, DM);
    gemm_bias<<<dim3((DM / GROUP) / 64, SEQ / 64), 256>>>(k, Wk, bk, gK, SEQ, DM / GROUP, DM);
    gemm_bias<<<dim3((DM / GROUP) / 64, SEQ / 64), 256>>>(v, Wv, bv, gV, SEQ, DM / GROUP, DM);

    // RoPE on Q and K
    {
        int tq = SEQ * HEADS * (HD / 2);
        rope_kernel<<<(tq + 255) / 256, 256>>>(gQ, HEADS);
        int tk = SEQ * KVH * (HD / 2);
        rope_kernel<<<(tk + 255) / 256, 256>>>(gK, KVH);
    }

    // attention
    attn_kernel<<<dim3(SEQ / 64, HEADS), 256>>>();

    // output projection
    gemm_bias<<<dim3(DM / 64, SEQ / 64), 256>>>(gO, Wo, bo, out, SEQ, DM, DM);
}

// round 11
// speedup vs baseline: 1.8608x; 1.8608x over previous
#include <cuda_runtime.h>
#include <math.h>
#include <cstdint>

#define SEQ   2048
#define DM    1024
#define HEADS 16
#define KVH   4
#define HD    64
#define GROUP 4

__device__ float g_Q[SEQ * DM];
__device__ float g_K[SEQ * KVH * HD];
__device__ float g_V[SEQ * KVH * HD];
__device__ float g_O[SEQ * DM];
__device__ float g_WqT[DM * DM];
__device__ float g_WkT[(DM / GROUP) * DM];
__device__ float g_WvT[(DM / GROUP) * DM];
__device__ float g_WoT[DM * DM];

__device__ __forceinline__ uint32_t cvt_tf32(float x) {
    uint32_t r;
    asm("cvt.rna.tf32.f32 %0, %1;" : "=r"(r) : "f"(x));
    return r;
}

#define MMA_TF32(d0,d1,d2,d3,a0,a1,a2,a3,b0,b1)                                   \
    asm volatile("mma.sync.aligned.m16n8k8.row.col.f32.tf32.tf32.f32 "            \
                 "{%0,%1,%2,%3}, {%4,%5,%6,%7}, {%8,%9}, {%0,%1,%2,%3};"          \
                 : "+f"(d0), "+f"(d1), "+f"(d2), "+f"(d3)                         \
                 : "r"(a0), "r"(a1), "r"(a2), "r"(a3), "r"(b0), "r"(b1))

// ---------------------------------------------------------------------------
// Weight transpose: Wt[n][k] = W[k][n]
// ---------------------------------------------------------------------------
__global__ void transpose_k(const float* __restrict__ W, float* __restrict__ Wt,
                            int K, int N) {
    __shared__ float t[32][33];
    int n0 = blockIdx.x * 32, k0 = blockIdx.y * 32;
    int tx = threadIdx.x, ty = threadIdx.y;
    #pragma unroll
    for (int i = 0; i < 32; i += 8)
        t[ty + i][tx] = W[(size_t)(k0 + ty + i) * N + n0 + tx];
    __syncthreads();
    #pragma unroll
    for (int i = 0; i < 32; i += 8)
        Wt[(size_t)(n0 + ty + i) * K + k0 + tx] = t[tx][ty + i];
}

// ---------------------------------------------------------------------------
// tf32 mma.sync GEMM + bias: C[M,N] = A[M,K] @ Bt[N,K]^T + bias
// BM=BN=128, BK=16, 256 threads (8 warps, 4x2), warp tile 32x64.
// ---------------------------------------------------------------------------
__global__ void __launch_bounds__(256)
gemm_mma(const float* __restrict__ A, const float* __restrict__ Bt,
         const float* __restrict__ bias, float* __restrict__ C,
         int N, int K) {
    __shared__ float As[128][20];
    __shared__ float Bs[128][20];

    int tid = threadIdx.x;
    int wid = tid >> 5, lane = tid & 31;
    int wm = (wid & 3) * 32;
    int wn = (wid >> 2) * 64;
    int r = lane >> 2, c = lane & 3;
    int row0 = blockIdx.y * 128, col0 = blockIdx.x * 128;

    float acc[2][8][4];
    #pragma unroll
    for (int mt = 0; mt < 2; mt++)
        #pragma unroll
        for (int nt = 0; nt < 8; nt++)
            #pragma unroll
            for (int e = 0; e < 4; e++) acc[mt][nt][e] = 0.0f;

    int lm = tid >> 1;
    int lk = (tid & 1) * 8;
    const float* arow = A  + (size_t)(row0 + lm) * K + lk;
    const float* brow = Bt + (size_t)(col0 + lm) * K + lk;

    for (int k0 = 0; k0 < K; k0 += 16) {
        float4 a0 = *(const float4*)(arow + k0);
        float4 a1 = *(const float4*)(arow + k0 + 4);
        float4 b0 = *(const float4*)(brow + k0);
        float4 b1 = *(const float4*)(brow + k0 + 4);
        uint4 ta0, ta1, tb0, tb1;
        ta0.x = cvt_tf32(a0.x); ta0.y = cvt_tf32(a0.y); ta0.z = cvt_tf32(a0.z); ta0.w = cvt_tf32(a0.w);
        ta1.x = cvt_tf32(a1.x); ta1.y = cvt_tf32(a1.y); ta1.z = cvt_tf32(a1.z); ta1.w = cvt_tf32(a1.w);
        tb0.x = cvt_tf32(b0.x); tb0.y = cvt_tf32(b0.y); tb0.z = cvt_tf32(b0.z); tb0.w = cvt_tf32(b0.w);
        tb1.x = cvt_tf32(b1.x); tb1.y = cvt_tf32(b1.y); tb1.z = cvt_tf32(b1.z); tb1.w = cvt_tf32(b1.w);
        __syncthreads();
        *(uint4*)&As[lm][lk]     = ta0;
        *(uint4*)&As[lm][lk + 4] = ta1;
        *(uint4*)&Bs[lm][lk]     = tb0;
        *(uint4*)&Bs[lm][lk + 4] = tb1;
        __syncthreads();

        #pragma unroll
        for (int ks = 0; ks < 16; ks += 8) {
            uint32_t af[2][4];
            #pragma unroll
            for (int mt = 0; mt < 2; mt++) {
                int m = wm + mt * 16 + r;
                af[mt][0] = __float_as_uint(As[m][ks + c]);
                af[mt][1] = __float_as_uint(As[m + 8][ks + c]);
                af[mt][2] = __float_as_uint(As[m][ks + c + 4]);
                af[mt][3] = __float_as_uint(As[m + 8][ks + c + 4]);
            }
            #pragma unroll
            for (int nt = 0; nt < 8; nt++) {
                int n = wn + nt * 8 + r;
                uint32_t bf0 = __float_as_uint(Bs[n][ks + c]);
                uint32_t bf1 = __float_as_uint(Bs[n][ks + c + 4]);
                #pragma unroll
                for (int mt = 0; mt < 2; mt++)
                    MMA_TF32(acc[mt][nt][0], acc[mt][nt][1], acc[mt][nt][2], acc[mt][nt][3],
                             af[mt][0], af[mt][1], af[mt][2], af[mt][3], bf0, bf1);
            }
        }
    }

    #pragma unroll
    for (int mt = 0; mt < 2; mt++) {
        int m = row0 + wm + mt * 16 + r;
        #pragma unroll
        for (int nt = 0; nt < 8; nt++) {
            int col = col0 + wn + nt * 8 + 2 * c;
            float b0 = bias[col], b1 = bias[col + 1];
            float2 lo = make_float2(acc[mt][nt][0] + b0, acc[mt][nt][1] + b1);
            float2 hi = make_float2(acc[mt][nt][2] + b0, acc[mt][nt][3] + b1);
            *(float2*)(C + (size_t)m * N + col)       = lo;
            *(float2*)(C + (size_t)(m + 8) * N + col) = hi;
        }
    }
}

// ---------------------------------------------------------------------------
// RoPE (interleaved pairs, reference convention)
// ---------------------------------------------------------------------------
__global__ void rope_kernel(float* __restrict__ X, int Hn) {
    int g = blockIdx.x * blockDim.x + threadIdx.x;
    int total = SEQ * Hn * (HD / 2);
    if (g >= total) return;
    int i = g % (HD / 2);
    int h = (g / (HD / 2)) % Hn;
    int s = g / ((HD / 2) * Hn);
    float inv = powf(10000.0f, -(float)(2 * (2 * i)) / (float)HD);
    float fr = (float)s * inv;
    float sv, cv;
    sincosf(fr, &sv, &cv);
    float* p = X + ((size_t)s * Hn + h) * HD + 2 * i;
    float x0 = p[0], x1 = p[1];
    p[0] = x0 * cv - x1 * sv;
    p[1] = x0 * sv + x1 * cv;
}

// ---------------------------------------------------------------------------
// Causal flash attention, fp32 — the R3 version that PASSED (rel_err 1e-6).
// ---------------------------------------------------------------------------
__global__ void attn_kernel() {
    __shared__ float Qs[64][68];
    __shared__ float Ks[32][68];
    __shared__ float Vs[32][68];
    __shared__ float Ps[64][34];

    int tid = threadIdx.x;
    int qr = tid >> 2;
    int c4 = tid & 3;
    int q0 = blockIdx.x * 64;
    int h  = blockIdx.y;
    int kvh = h % KVH;

    #pragma unroll
    for (int i = 0; i < 4; i++) {
        int f = tid + i * 256;
        int r = f >> 4, d4 = (f & 15) * 4;
        *(float4*)&Qs[r][d4] =
            *(const float4*)(g_Q + ((size_t)(q0 + r) * HEADS + h) * HD + d4);
    }

    float acc[4][4] = {};
    float mprev = -INFINITY, lrow = 0.0f;
    int ntiles = q0 / 32 + 2;

    for (int kt = 0; kt < ntiles; kt++) {
        int k0 = kt * 32;
        __syncthreads();
        #pragma unroll
        for (int i = 0; i < 2; i++) {
            int f = tid + i * 256;
            int r = f >> 4, d4 = (f & 15) * 4;
            size_t off = ((size_t)(k0 + r) * KVH + kvh) * HD + d4;
            *(float4*)&Ks[r][d4] = *(const float4*)(g_K + off);
            *(float4*)&Vs[r][d4] = *(const float4*)(g_V + off);
        }
        __syncthreads();

        float s[8];
        #pragma unroll
        for (int jj = 0; jj < 8; jj++) {
            int j = jj * 4 + c4;
            float a = 0.0f;
            #pragma unroll
            for (int d = 0; d < 64; d++) a += Qs[qr][d] * Ks[j][d];
            s[jj] = a * 0.125f;
        }
        if (k0 + 31 > q0 + qr) {
            #pragma unroll
            for (int jj = 0; jj < 8; jj++)
                if (k0 + jj * 4 + c4 > q0 + qr) s[jj] = -INFINITY;
        }

        float mloc = s[0];
        #pragma unroll
        for (int jj = 1; jj < 8; jj++) mloc = fmaxf(mloc, s[jj]);
        mloc = fmaxf(mloc, __shfl_xor_sync(0xffffffff, mloc, 1));
        mloc = fmaxf(mloc, __shfl_xor_sync(0xffffffff, mloc, 2));
        float mnew = fmaxf(mprev, mloc);
        float corr = __expf(mprev - mnew);
        float psum = 0.0f;
        #pragma unroll
        for (int jj = 0; jj < 8; jj++) {
            float p = __expf(s[jj] - mnew);
            Ps[qr][jj * 4 + c4] = p;
            psum += p;
        }
        psum += __shfl_xor_sync(0xffffffff, psum, 1);
        psum += __shfl_xor_sync(0xffffffff, psum, 2);
        lrow = lrow * corr + psum;
        mprev = mnew;
        #pragma unroll
        for (int g = 0; g < 4; g++)
            #pragma unroll
            for (int e = 0; e < 4; e++) acc[g][e] *= corr;

        __syncwarp();

        #pragma unroll 4
        for (int k = 0; k < 32; k++) {
            float p = Ps[qr][k];
            #pragma unroll
            for (int g = 0; g < 4; g++) {
                float4 v = *(float4*)&Vs[k][g * 16 + c4 * 4];
                acc[g][0] += p * v.x; acc[g][1] += p * v.y;
                acc[g][2] += p * v.z; acc[g][3] += p * v.w;
            }
        }
    }

    float invl = 1.0f / lrow;
    float* outp = g_O + ((size_t)(q0 + qr) * HEADS + h) * HD;
    #pragma unroll
    for (int g = 0; g < 4; g++) {
        float4 v;
        v.x = acc[g][0] * invl; v.y = acc[g][1] * invl;
        v.z = acc[g][2] * invl; v.w = acc[g][3] * invl;
        *(float4*)(outp + g * 16 + c4 * 4) = v;
    }
}

// ---------------------------------------------------------------------------
// Launch.  Inputs: q,k,v,mask,Wq,bq,Wk,bk,Wv,bv,Wo,bo
// ---------------------------------------------------------------------------
extern "C" void kernel_launch(void* const* d_in, const int* in_sizes, int n_in,
                              void* d_out, int out_size) {
    const float* q  = (const float*)d_in[0];
    const float* k  = (const float*)d_in[1];
    const float* v  = (const float*)d_in[2];
    const float* Wq = (const float*)d_in[4];
    const float* bq = (const float*)d_in[5];
    const float* Wk = (const float*)d_in[6];
    const float* bk = (const float*)d_in[7];
    const float* Wv = (const float*)d_in[8];
    const float* bv = (const float*)d_in[9];
    const float* Wo = (const float*)d_in[10];
    const float* bo = (const float*)d_in[11];
    float* out = (float*)d_out;

    float *gQ, *gK, *gV, *gO, *wqT, *wkT, *wvT, *woT;
    cudaGetSymbolAddress((void**)&gQ, g_Q);
    cudaGetSymbolAddress((void**)&gK, g_K);
    cudaGetSymbolAddress((void**)&gV, g_V);
    cudaGetSymbolAddress((void**)&gO, g_O);
    cudaGetSymbolAddress((void**)&wqT, g_WqT);
    cudaGetSymbolAddress((void**)&wkT, g_WkT);
    cudaGetSymbolAddress((void**)&wvT, g_WvT);
    cudaGetSymbolAddress((void**)&woT, g_WoT);

    dim3 tb(32, 8);
    transpose_k<<<dim3(DM / 32, DM / 32), tb>>>(Wq, wqT, DM, DM);
    transpose_k<<<dim3((DM / GROUP) / 32, DM / 32), tb>>>(Wk, wkT, DM, DM / GROUP);
    transpose_k<<<dim3((DM / GROUP) / 32, DM / 32), tb>>>(Wv, wvT, DM, DM / GROUP);
    transpose_k<<<dim3(DM / 32, DM / 32), tb>>>(Wo, woT, DM, DM);

    // projections (tf32 mma.sync)
    gemm_mma<<<dim3(DM / 128, SEQ / 128), 256>>>(q, wqT, bq, gQ, DM, DM);
    gemm_mma<<<dim3((DM / GROUP) / 128, SEQ / 128), 256>>>(k, wkT, bk, gK, DM / GROUP, DM);
    gemm_mma<<<dim3((DM / GROUP) / 128, SEQ / 128), 256>>>(v, wvT, bv, gV, DM / GROUP, DM);

    // RoPE
    {
        int tq = SEQ * HEADS * (HD / 2);
        rope_kernel<<<(tq + 255) / 256, 256>>>(gQ, HEADS);
        int tk = SEQ * KVH * (HD / 2);
        rope_kernel<<<(tk + 255) / 256, 256>>>(gK, KVH);
    }

    // attention (known-good scalar fp32)
    attn_kernel<<<dim3(SEQ / 64, HEADS), 256>>>();

    // output projection (tf32 mma.sync)
    gemm_mma<<<dim3(DM / 128, SEQ / 128), 256>>>(gO, woT, bo, out, DM, DM);
}

// round 14
// speedup vs baseline: 4.1140x; 2.2109x over previous
#include <cuda_runtime.h>
#include <math.h>
#include <cstdint>

#define SEQ   2048
#define DM    1024
#define HEADS 16
#define KVH   4
#define HD    64
#define GROUP 4

__device__ float g_Q[SEQ * DM];
__device__ float g_K[SEQ * KVH * HD];
__device__ float g_V[SEQ * KVH * HD];
__device__ float g_O[SEQ * DM];
__device__ float g_WqT[DM * DM];
__device__ float g_WkT[(DM / GROUP) * DM];
__device__ float g_WvT[(DM / GROUP) * DM];
__device__ float g_WoT[DM * DM];

__device__ __forceinline__ uint32_t cvt_tf32(float x) {
    uint32_t r;
    asm("cvt.rna.tf32.f32 %0, %1;" : "=r"(r) : "f"(x));
    return r;
}

#define MMA_TF32(d0,d1,d2,d3,a0,a1,a2,a3,b0,b1)                                   \
    asm volatile("mma.sync.aligned.m16n8k8.row.col.f32.tf32.tf32.f32 "            \
                 "{%0,%1,%2,%3}, {%4,%5,%6,%7}, {%8,%9}, {%0,%1,%2,%3};"          \
                 : "+f"(d0), "+f"(d1), "+f"(d2), "+f"(d3)                         \
                 : "r"(a0), "r"(a1), "r"(a2), "r"(a3), "r"(b0), "r"(b1))

// ---------------------------------------------------------------------------
// Weight transpose: Wt[n][k] = W[k][n]
// ---------------------------------------------------------------------------
__global__ void transpose_k(const float* __restrict__ W, float* __restrict__ Wt,
                            int K, int N) {
    __shared__ float t[32][33];
    int n0 = blockIdx.x * 32, k0 = blockIdx.y * 32;
    int tx = threadIdx.x, ty = threadIdx.y;
    #pragma unroll
    for (int i = 0; i < 32; i += 8)
        t[ty + i][tx] = W[(size_t)(k0 + ty + i) * N + n0 + tx];
    __syncthreads();
    #pragma unroll
    for (int i = 0; i < 32; i += 8)
        Wt[(size_t)(n0 + ty + i) * K + k0 + tx] = t[tx][ty + i];
}

// ---------------------------------------------------------------------------
// tf32 mma.sync GEMM + bias (proven correct in R11)
// ---------------------------------------------------------------------------
__global__ void __launch_bounds__(256)
gemm_mma(const float* __restrict__ A, const float* __restrict__ Bt,
         const float* __restrict__ bias, float* __restrict__ C,
         int N, int K) {
    __shared__ float As[128][20];
    __shared__ float Bs[128][20];

    int tid = threadIdx.x;
    int wid = tid >> 5, lane = tid & 31;
    int wm = (wid & 3) * 32;
    int wn = (wid >> 2) * 64;
    int r = lane >> 2, c = lane & 3;
    int row0 = blockIdx.y * 128, col0 = blockIdx.x * 128;

    float acc[2][8][4];
    #pragma unroll
    for (int mt = 0; mt < 2; mt++)
        #pragma unroll
        for (int nt = 0; nt < 8; nt++)
            #pragma unroll
            for (int e = 0; e < 4; e++) acc[mt][nt][e] = 0.0f;

    int lm = tid >> 1;
    int lk = (tid & 1) * 8;
    const float* arow = A  + (size_t)(row0 + lm) * K + lk;
    const float* brow = Bt + (size_t)(col0 + lm) * K + lk;

    for (int k0 = 0; k0 < K; k0 += 16) {
        float4 a0 = *(const float4*)(arow + k0);
        float4 a1 = *(const float4*)(arow + k0 + 4);
        float4 b0 = *(const float4*)(brow + k0);
        float4 b1 = *(const float4*)(brow + k0 + 4);
        uint4 ta0, ta1, tb0, tb1;
        ta0.x = cvt_tf32(a0.x); ta0.y = cvt_tf32(a0.y); ta0.z = cvt_tf32(a0.z); ta0.w = cvt_tf32(a0.w);
        ta1.x = cvt_tf32(a1.x); ta1.y = cvt_tf32(a1.y); ta1.z = cvt_tf32(a1.z); ta1.w = cvt_tf32(a1.w);
        tb0.x = cvt_tf32(b0.x); tb0.y = cvt_tf32(b0.y); tb0.z = cvt_tf32(b0.z); tb0.w = cvt_tf32(b0.w);
        tb1.x = cvt_tf32(b1.x); tb1.y = cvt_tf32(b1.y); tb1.z = cvt_tf32(b1.z); tb1.w = cvt_tf32(b1.w);
        __syncthreads();
        *(uint4*)&As[lm][lk]     = ta0;
        *(uint4*)&As[lm][lk + 4] = ta1;
        *(uint4*)&Bs[lm][lk]     = tb0;
        *(uint4*)&Bs[lm][lk + 4] = tb1;
        __syncthreads();

        #pragma unroll
        for (int ks = 0; ks < 16; ks += 8) {
            uint32_t af[2][4];
            #pragma unroll
            for (int mt = 0; mt < 2; mt++) {
                int m = wm + mt * 16 + r;
                af[mt][0] = __float_as_uint(As[m][ks + c]);
                af[mt][1] = __float_as_uint(As[m + 8][ks + c]);
                af[mt][2] = __float_as_uint(As[m][ks + c + 4]);
                af[mt][3] = __float_as_uint(As[m + 8][ks + c + 4]);
            }
            #pragma unroll
            for (int nt = 0; nt < 8; nt++) {
                int n = wn + nt * 8 + r;
                uint32_t bf0 = __float_as_uint(Bs[n][ks + c]);
                uint32_t bf1 = __float_as_uint(Bs[n][ks + c + 4]);
                #pragma unroll
                for (int mt = 0; mt < 2; mt++)
                    MMA_TF32(acc[mt][nt][0], acc[mt][nt][1], acc[mt][nt][2], acc[mt][nt][3],
                             af[mt][0], af[mt][1], af[mt][2], af[mt][3], bf0, bf1);
            }
        }
    }

    #pragma unroll
    for (int mt = 0; mt < 2; mt++) {
        int m = row0 + wm + mt * 16 + r;
        #pragma unroll
        for (int nt = 0; nt < 8; nt++) {
            int col = col0 + wn + nt * 8 + 2 * c;
            float b0 = bias[col], b1 = bias[col + 1];
            float2 lo = make_float2(acc[mt][nt][0] + b0, acc[mt][nt][1] + b1);
            float2 hi = make_float2(acc[mt][nt][2] + b0, acc[mt][nt][3] + b1);
            *(float2*)(C + (size_t)m * N + col)       = lo;
            *(float2*)(C + (size_t)(m + 8) * N + col) = hi;
        }
    }
}

// ---------------------------------------------------------------------------
// RoPE (interleaved pairs, reference convention)
// ---------------------------------------------------------------------------
__global__ void rope_kernel(float* __restrict__ X, int Hn) {
    int g = blockIdx.x * blockDim.x + threadIdx.x;
    int total = SEQ * Hn * (HD / 2);
    if (g >= total) return;
    int i = g % (HD / 2);
    int h = (g / (HD / 2)) % Hn;
    int s = g / ((HD / 2) * Hn);
    float inv = powf(10000.0f, -(float)(2 * (2 * i)) / (float)HD);
    float fr = (float)s * inv;
    float sv, cv;
    sincosf(fr, &sv, &cv);
    float* p = X + ((size_t)s * Hn + h) * HD + 2 * i;
    float x0 = p[0], x1 = p[1];
    p[0] = x0 * cv - x1 * sv;
    p[1] = x0 * sv + x1 * cv;
}

// ---------------------------------------------------------------------------
// Tensor-core causal flash attention (tf32 mma.sync), CORRECT SMEM strides.
// grid (SEQ/64, HEADS), 128 threads = 4 warps; warp w owns 16 q-rows.
// BQ=64, BK=32, hd=64. Q/K/V tiles are 64 columns wide -> stride 68.
// ---------------------------------------------------------------------------
__global__ void __launch_bounds__(128) attn_mma() {
    __shared__ float Qs[64][68];
    __shared__ float Ks[32][68];
    __shared__ float Vs[32][68];
    __shared__ float Ps[64][36];

    int tid = threadIdx.x, w = tid >> 5, lane = tid & 31;
    int r = lane >> 2, c = lane & 3;
    int q0 = blockIdx.x * 64, h = blockIdx.y, kvh = h % KVH;
    int qrow = w * 16 + r;

    // stage Q (tf32-rounded)
    #pragma unroll
    for (int i = 0; i < 8; i++) {
        int f = tid + i * 128;
        int row = f >> 4, d4 = (f & 15) * 4;
        float4 qv = *(const float4*)(g_Q + ((size_t)(q0 + row) * HEADS + h) * HD + d4);
        uint4 tq;
        tq.x = cvt_tf32(qv.x); tq.y = cvt_tf32(qv.y);
        tq.z = cvt_tf32(qv.z); tq.w = cvt_tf32(qv.w);
        *(uint4*)&Qs[row][d4] = tq;
    }
    __syncthreads();

    // preload Q fragments
    uint32_t qf[8][4];
    #pragma unroll
    for (int ks = 0; ks < 8; ks++) {
        qf[ks][0] = __float_as_uint(Qs[qrow][ks * 8 + c]);
        qf[ks][1] = __float_as_uint(Qs[qrow + 8][ks * 8 + c]);
        qf[ks][2] = __float_as_uint(Qs[qrow][ks * 8 + c + 4]);
        qf[ks][3] = __float_as_uint(Qs[qrow + 8][ks * 8 + c + 4]);
    }

    float acc_o[8][4];
    #pragma unroll
    for (int nt = 0; nt < 8; nt++)
        #pragma unroll
        for (int e = 0; e < 4; e++) acc_o[nt][e] = 0.0f;
    float m0 = -INFINITY, m1 = -INFINITY, l0 = 0.0f, l1 = 0.0f;

    int ntiles = q0 / 32 + 2;
    for (int kt = 0; kt < ntiles; kt++) {
        int k0 = kt * 32;
        __syncthreads();
        #pragma unroll
        for (int i = 0; i < 4; i++) {
            int f = tid + i * 128;
            int row = f >> 4, d4 = (f & 15) * 4;
            size_t off = ((size_t)(k0 + row) * KVH + kvh) * HD + d4;
            float4 kv = *(const float4*)(g_K + off);
            float4 vv = *(const float4*)(g_V + off);
            uint4 tk, tv;
            tk.x = cvt_tf32(kv.x); tk.y = cvt_tf32(kv.y);
            tk.z = cvt_tf32(kv.z); tk.w = cvt_tf32(kv.w);
            tv.x = cvt_tf32(vv.x); tv.y = cvt_tf32(vv.y);
            tv.z = cvt_tf32(vv.z); tv.w = cvt_tf32(vv.w);
            *(uint4*)&Ks[row][d4] = tk;
            *(uint4*)&Vs[row][d4] = tv;
        }
        __syncthreads();

        // S = Q @ K^T
        float acc_s[4][4];
        #pragma unroll
        for (int nt = 0; nt < 4; nt++)
            #pragma unroll
            for (int e = 0; e < 4; e++) acc_s[nt][e] = 0.0f;
        #pragma unroll
        for (int ks = 0; ks < 8; ks++) {
            #pragma unroll
            for (int nt = 0; nt < 4; nt++) {
                uint32_t bf0 = __float_as_uint(Ks[nt * 8 + r][ks * 8 + c]);
                uint32_t bf1 = __float_as_uint(Ks[nt * 8 + r][ks * 8 + c + 4]);
                MMA_TF32(acc_s[nt][0], acc_s[nt][1], acc_s[nt][2], acc_s[nt][3],
                         qf[ks][0], qf[ks][1], qf[ks][2], qf[ks][3], bf0, bf1);
            }
        }

        // scale + causal mask + running max
        float mt0 = m0, mt1 = m1;
        bool need_mask = (k0 + 31 > q0);
        #pragma unroll
        for (int nt = 0; nt < 4; nt++) {
            #pragma unroll
            for (int e = 0; e < 4; e++) {
                float s = acc_s[nt][e] * 0.125f;
                if (need_mask) {
                    int col = k0 + nt * 8 + 2 * c + (e & 1);
                    int row = q0 + qrow + ((e >= 2) ? 8 : 0);
                    if (col > row) s = -INFINITY;
                }
                acc_s[nt][e] = s;
            }
            mt0 = fmaxf(mt0, fmaxf(acc_s[nt][0], acc_s[nt][1]));
            mt1 = fmaxf(mt1, fmaxf(acc_s[nt][2], acc_s[nt][3]));
        }
        mt0 = fmaxf(mt0, __shfl_xor_sync(0xffffffff, mt0, 1));
        mt0 = fmaxf(mt0, __shfl_xor_sync(0xffffffff, mt0, 2));
        mt1 = fmaxf(mt1, __shfl_xor_sync(0xffffffff, mt1, 1));
        mt1 = fmaxf(mt1, __shfl_xor_sync(0xffffffff, mt1, 2));
        float corr0 = __expf(m0 - mt0);
        float corr1 = __expf(m1 - mt1);
        m0 = mt0; m1 = mt1;

        float ps0 = 0.0f, ps1 = 0.0f;
        #pragma unroll
        for (int nt = 0; nt < 4; nt++) {
            float p0 = __uint_as_float(cvt_tf32(__expf(acc_s[nt][0] - m0)));
            float p1 = __uint_as_float(cvt_tf32(__expf(acc_s[nt][1] - m0)));
            float p2 = __uint_as_float(cvt_tf32(__expf(acc_s[nt][2] - m1)));
            float p3 = __uint_as_float(cvt_tf32(__expf(acc_s[nt][3] - m1)));
            Ps[qrow][nt * 8 + 2 * c]         = p0;
            Ps[qrow][nt * 8 + 2 * c + 1]     = p1;
            Ps[qrow + 8][nt * 8 + 2 * c]     = p2;
            Ps[qrow + 8][nt * 8 + 2 * c + 1] = p3;
            ps0 += p0 + p1;
            ps1 += p2 + p3;
        }
        ps0 += __shfl_xor_sync(0xffffffff, ps0, 1);
        ps0 += __shfl_xor_sync(0xffffffff, ps0, 2);
        ps1 += __shfl_xor_sync(0xffffffff, ps1, 1);
        ps1 += __shfl_xor_sync(0xffffffff, ps1, 2);
        l0 = l0 * corr0 + ps0;
        l1 = l1 * corr1 + ps1;
        #pragma unroll
        for (int nt = 0; nt < 8; nt++) {
            acc_o[nt][0] *= corr0; acc_o[nt][1] *= corr0;
            acc_o[nt][2] *= corr1; acc_o[nt][3] *= corr1;
        }
        __syncwarp();   // Ps rows are warp-private

        // O += P @ V   (B[k=key][n=dim] = Vs[key][dim], col-major fragments)
        #pragma unroll
        for (int ks = 0; ks < 4; ks++) {
            uint32_t af0 = __float_as_uint(Ps[qrow][ks * 8 + c]);
            uint32_t af1 = __float_as_uint(Ps[qrow + 8][ks * 8 + c]);
            uint32_t af2 = __float_as_uint(Ps[qrow][ks * 8 + c + 4]);
            uint32_t af3 = __float_as_uint(Ps[qrow + 8][ks * 8 + c + 4]);
            #pragma unroll
            for (int nt = 0; nt < 8; nt++) {
                uint32_t bf0 = __float_as_uint(Vs[ks * 8 + c][nt * 8 + r]);
                uint32_t bf1 = __float_as_uint(Vs[ks * 8 + c + 4][nt * 8 + r]);
                MMA_TF32(acc_o[nt][0], acc_o[nt][1], acc_o[nt][2], acc_o[nt][3],
                         af0, af1, af2, af3, bf0, bf1);
            }
        }
    }

    float inv0 = 1.0f / l0, inv1 = 1.0f / l1;
    float* o0 = g_O + ((size_t)(q0 + qrow) * HEADS + h) * HD;
    float* o1 = g_O + ((size_t)(q0 + qrow + 8) * HEADS + h) * HD;
    #pragma unroll
    for (int nt = 0; nt < 8; nt++) {
        int col = nt * 8 + 2 * c;
        *(float2*)(o0 + col) = make_float2(acc_o[nt][0] * inv0, acc_o[nt][1] * inv0);
        *(float2*)(o1 + col) = make_float2(acc_o[nt][2] * inv1, acc_o[nt][3] * inv1);
    }
}

// ---------------------------------------------------------------------------
// Launch.  Inputs: q,k,v,mask,Wq,bq,Wk,bk,Wv,bv,Wo,bo
// ---------------------------------------------------------------------------
extern "C" void kernel_launch(void* const* d_in, const int* in_sizes, int n_in,
                              void* d_out, int out_size) {
    const float* q  = (const float*)d_in[0];
    const float* k  = (const float*)d_in[1];
    const float* v  = (const float*)d_in[2];
    const float* Wq = (const float*)d_in[4];
    const float* bq = (const float*)d_in[5];
    const float* Wk = (const float*)d_in[6];
    const float* bk = (const float*)d_in[7];
    const float* Wv = (const float*)d_in[8];
    const float* bv = (const float*)d_in[9];
    const float* Wo = (const float*)d_in[10];
    const float* bo = (const float*)d_in[11];
    float* out = (float*)d_out;

    float *gQ, *gK, *gV, *gO, *wqT, *wkT, *wvT, *woT;
    cudaGetSymbolAddress((void**)&gQ, g_Q);
    cudaGetSymbolAddress((void**)&gK, g_K);
    cudaGetSymbolAddress((void**)&gV, g_V);
    cudaGetSymbolAddress((void**)&gO, g_O);
    cudaGetSymbolAddress((void**)&wqT, g_WqT);
    cudaGetSymbolAddress((void**)&wkT, g_WkT);
    cudaGetSymbolAddress((void**)&wvT, g_WvT);
    cudaGetSymbolAddress((void**)&woT, g_WoT);

    dim3 tb(32, 8);
    transpose_k<<<dim3(DM / 32, DM / 32), tb>>>(Wq, wqT, DM, DM);
    transpose_k<<<dim3((DM / GROUP) / 32, DM / 32), tb>>>(Wk, wkT, DM, DM / GROUP);
    transpose_k<<<dim3((DM / GROUP) / 32, DM / 32), tb>>>(Wv, wvT, DM, DM / GROUP);
    transpose_k<<<dim3(DM / 32, DM / 32), tb>>>(Wo, woT, DM, DM);

    // projections (tf32 mma.sync)
    gemm_mma<<<dim3(DM / 128, SEQ / 128), 256>>>(q, wqT, bq, gQ, DM, DM);
    gemm_mma<<<dim3((DM / GROUP) / 128, SEQ / 128), 256>>>(k, wkT, bk, gK, DM / GROUP, DM);
    gemm_mma<<<dim3((DM / GROUP) / 128, SEQ / 128), 256>>>(v, wvT, bv, gV, DM / GROUP, DM);

    // RoPE
    {
        int tq = SEQ * HEADS * (HD / 2);
        rope_kernel<<<(tq + 255) / 256, 256>>>(gQ, HEADS);
        int tk = SEQ * KVH * (HD / 2);
        rope_kernel<<<(tk + 255) / 256, 256>>>(gK, KVH);
    }

    // attention (full tf32 mma)
    attn_mma<<<dim3(SEQ / 64, HEADS), 128>>>();

    // output projection (tf32 mma.sync)
    gemm_mma<<<dim3(DM / 128, SEQ / 128), 256>>>(gO, woT, bo, out, DM, DM);
}